// round 1
// baseline (speedup 1.0000x reference)
#include <cuda_runtime.h>
#include <cuda_bf16.h>

// Problem constants (fixed shapes from setup_inputs)
#define DIM   2048
#define HWTOT (DIM * DIM)
#define HW4   (HWTOT / 4)
#define NW    4
// Aperture: |x_i| <= 0.04 with x_i = -0.1024 + i * (0.2048/2047)
// -> i in [624, 1423] (margin ~7e-5 m, fp32-safe). 624 % 4 == 0, 1424 % 4 == 0,
// so every float4 group of columns is uniformly inside or outside.
#define AP_LO 624
#define AP_HI 1423

__device__ __forceinline__ float floormod4(float x) {
    // x - 4*floor(x/4)  (matches jnp.mod semantics for divisor 4)
    return x - 4.0f * floorf(x * 0.25f);
}

__global__ void __launch_bounds__(256)
sgqm_kernel(const float* __restrict__ init_mask,   // [HWTOT]
            const float* __restrict__ lut,         // [2]
            const float* __restrict__ field_r,     // [NW*HWTOT]
            const float* __restrict__ field_i,     // [NW*HWTOT]
            const float* __restrict__ wl,          // [NW]
            const float* __restrict__ gumbel,      // [2*HWTOT]
            const float* __restrict__ epsilon,     // [1]
            const float* __restrict__ tandp,       // [1]
            float* __restrict__ out)               // [2*NW*HWTOT]
{
    const int g = blockIdx.x * blockDim.x + threadIdx.x;  // float4 group index
    if (g >= HW4) return;

    const int p = g << 2;            // first pixel of this group
    const int y = p >> 11;           // row    (DIM = 2048 = 1<<11)
    const int x = p & (DIM - 1);     // column of first pixel

    float4* __restrict__ out4 = (float4*)out;

    const bool inside = (y >= AP_LO) & (y <= AP_HI) & (x >= AP_LO) & (x <= AP_HI);

    if (!inside) {
        // Pure streaming zero-fill: 8 float4 stores (4 wavelengths x re/im)
        const float4 z = make_float4(0.f, 0.f, 0.f, 0.f);
        #pragma unroll
        for (int w = 0; w < NW; w++) {
            out4[w * HW4 + g]        = z;   // real plane
            out4[(NW + w) * HW4 + g] = z;   // imag plane
        }
        return;
    }

    // ---- scalar parameters (L1/L2-cached broadcast loads) ----
    const float eps = __ldg(epsilon);
    const float td  = __ldg(tandp);
    const float sq  = sqrtf(eps);
    const float l0  = __ldg(lut);
    const float l1  = __ldg(lut + 1);
    float lam0 = __ldg(wl + 0), lam1 = __ldg(wl + 1);
    float lam2 = __ldg(wl + 2), lam3 = __ldg(wl + 3);
    const float lam_min = fminf(fminf(lam0, lam1), fminf(lam2, lam3));
    const float PI = 3.14159265358979323846f;
    // height = mask * pi / (2*pi/lam_min) / (sq-1) = mask * lam_min / (2*(sq-1))
    const float Ch     = lam_min / (2.0f * (sq - 1.0f));
    const float BASE_T = 2.0e-3f;
    const float S      = 5.0f;   // score sharpness
    // gumbel-softmax tau = 2 -> logits a = (score+g)/2

    // ---- per-pixel mask -> height (shared across wavelengths) ----
    const float4 m4  = ((const float4*)init_mask)[g];
    const float4 gn0 = ((const float4*)gumbel)[g];
    const float4 gn1 = ((const float4*)gumbel)[HW4 + g];

    const float mm[4]  = {m4.x,  m4.y,  m4.z,  m4.w};
    const float gg0[4] = {gn0.x, gn0.y, gn0.z, gn0.w};
    const float gg1[4] = {gn1.x, gn1.y, gn1.z, gn1.w};

    float h[4];
    #pragma unroll
    for (int i = 0; i < 4; i++) {
        const float wrapped = floormod4(mm[i] + 2.0f) - 2.0f;

        const float d0 = (floormod4(wrapped - l0 + 2.0f) - 2.0f) * 0.5f;
        const float s0 = 1.0f / (1.0f + expf(-S * d0));
        const float sc0 = 4.0f * s0 * (1.0f - s0);

        const float d1 = (floormod4(wrapped - l1 + 2.0f) - 2.0f) * 0.5f;
        const float s1 = 1.0f / (1.0f + expf(-S * d1));
        const float sc1 = 4.0f * s1 * (1.0f - s1);

        const float a0 = (sc0 + gg0[i]) * 0.5f;
        const float a1 = (sc1 + gg1[i]) * 0.5f;
        // softmax over 2 entries: p1 = sigmoid(a1-a0); mask = l0 + (l1-l0)*p1
        const float p1   = 1.0f / (1.0f + expf(-(a1 - a0)));
        const float mask = l0 + (l1 - l0) * p1;

        h[i] = mask * Ch + BASE_T;
    }

    const float lams[4] = {lam0, lam1, lam2, lam3};

    // ---- per-wavelength modulation ----
    #pragma unroll
    for (int w = 0; w < NW; w++) {
        const float k = 2.0f * PI / lams[w];
        const float A = -0.5f * k * td * sq;   // loss  = exp(A*h)
        const float B = k * (sq - 1.0f);       // phase = B*h, shift = loss*exp(-i*phase)

        const float4 fr = ((const float4*)field_r)[w * HW4 + g];
        const float4 fi = ((const float4*)field_i)[w * HW4 + g];
        const float frr[4] = {fr.x, fr.y, fr.z, fr.w};
        const float fii[4] = {fi.x, fi.y, fi.z, fi.w};

        float orr[4], oii[4];
        #pragma unroll
        for (int i = 0; i < 4; i++) {
            const float loss = expf(A * h[i]);
            float s, c;
            sincosf(B * h[i], &s, &c);
            const float psr =  loss * c;
            const float psi = -loss * s;
            // (fr + i*fi) * (psr + i*psi)
            orr[i] = frr[i] * psr - fii[i] * psi;
            oii[i] = frr[i] * psi + fii[i] * psr;
        }
        out4[w * HW4 + g]        = make_float4(orr[0], orr[1], orr[2], orr[3]);
        out4[(NW + w) * HW4 + g] = make_float4(oii[0], oii[1], oii[2], oii[3]);
    }
}

extern "C" void kernel_launch(void* const* d_in, const int* in_sizes, int n_in,
                              void* d_out, int out_size) {
    // metadata order: init_mask, lut, field_real, field_imag, wavelengths,
    //                 gumbel_noise, epsilon, tand
    const float* init_mask = (const float*)d_in[0];
    const float* lut       = (const float*)d_in[1];
    const float* field_r   = (const float*)d_in[2];
    const float* field_i   = (const float*)d_in[3];
    const float* wl        = (const float*)d_in[4];
    const float* gumbel    = (const float*)d_in[5];
    const float* eps       = (const float*)d_in[6];
    const float* td        = (const float*)d_in[7];

    const int threads = 256;
    const int blocks  = (HW4 + threads - 1) / threads;  // 4096
    sgqm_kernel<<<blocks, threads>>>(init_mask, lut, field_r, field_i,
                                     wl, gumbel, eps, td, (float*)d_out);
}

// round 3
// speedup vs baseline: 1.0563x; 1.0563x over previous
#include <cuda_runtime.h>
#include <cuda_bf16.h>

// Problem constants (fixed shapes from setup_inputs)
#define DIM   2048
#define HWTOT (DIM * DIM)
#define HW4   (HWTOT / 4)
#define NW    4
// Aperture: |x_i| <= 0.04 with x_i = -0.1024 + i * (0.2048/2047)
// -> i in [624, 1423] (margin ~7e-5 m, fp32-safe). 624 % 4 == 0, 1424 % 4 == 0,
// so every float4 group of columns is uniformly inside or outside.
#define AP_LO 624
#define AP_HI 1423

__device__ __forceinline__ float floormod4(float x) {
    // x - 4*floor(x/4)  (matches jnp.mod semantics for divisor 4)
    return x - 4.0f * floorf(x * 0.25f);
}

// fast sigmoid using intrinsic exp2-based exp and fast reciprocal
__device__ __forceinline__ float fsigmoid(float x) {
    return __fdividef(1.0f, 1.0f + __expf(-x));
}

__global__ void __launch_bounds__(256, 8)
sgqm_kernel(const float* __restrict__ init_mask,   // [HWTOT]
            const float* __restrict__ lut,         // [2]
            const float* __restrict__ field_r,     // [NW*HWTOT]
            const float* __restrict__ field_i,     // [NW*HWTOT]
            const float* __restrict__ wl,          // [NW]
            const float* __restrict__ gumbel,      // [2*HWTOT]
            const float* __restrict__ epsilon,     // [1]
            const float* __restrict__ tandp,       // [1]
            float* __restrict__ out)               // [2*NW*HWTOT]
{
    const int g = blockIdx.x * blockDim.x + threadIdx.x;  // float4 group index
    if (g >= HW4) return;

    const int p = g << 2;            // first pixel of this group
    const int y = p >> 11;           // row    (DIM = 2048 = 1<<11)
    const int x = p & (DIM - 1);     // column of first pixel

    float4* __restrict__ out4 = (float4*)out;

    const bool inside = (y >= AP_LO) & (y <= AP_HI) & (x >= AP_LO) & (x <= AP_HI);

    if (!inside) {
        // Pure streaming zero-fill: 8 float4 stores (4 wavelengths x re/im)
        const float4 z = make_float4(0.f, 0.f, 0.f, 0.f);
        #pragma unroll
        for (int w = 0; w < NW; w++) {
            __stcs(&out4[w * HW4 + g],        z);   // real plane
            __stcs(&out4[(NW + w) * HW4 + g], z);   // imag plane
        }
        return;
    }

    // ---- scalar parameters (L1/L2-cached broadcast loads) ----
    const float eps = __ldg(epsilon);
    const float td  = __ldg(tandp);
    const float sq  = sqrtf(eps);
    const float l0  = __ldg(lut);
    const float l1  = __ldg(lut + 1);
    const float lam0 = __ldg(wl + 0), lam1 = __ldg(wl + 1);
    const float lam2 = __ldg(wl + 2), lam3 = __ldg(wl + 3);
    const float lam_min = fminf(fminf(lam0, lam1), fminf(lam2, lam3));
    const float PI = 3.14159265358979323846f;
    // height = mask * pi / (2*pi/lam_min) / (sq-1) = mask * lam_min / (2*(sq-1))
    const float Ch     = lam_min / (2.0f * (sq - 1.0f));
    const float BASE_T = 2.0e-3f;
    const float S      = 5.0f;   // score sharpness
    // gumbel-softmax tau = 2 -> logits a = (score+g)/2

    // ---- per-pixel mask -> height (shared across wavelengths) ----
    const float4 m4  = __ldcs((const float4*)init_mask + g);
    const float4 gn0 = __ldcs((const float4*)gumbel + g);
    const float4 gn1 = __ldcs((const float4*)gumbel + HW4 + g);

    const float mm[4]  = {m4.x,  m4.y,  m4.z,  m4.w};
    const float gg0[4] = {gn0.x, gn0.y, gn0.z, gn0.w};
    const float gg1[4] = {gn1.x, gn1.y, gn1.z, gn1.w};

    float h[4];
    #pragma unroll
    for (int i = 0; i < 4; i++) {
        const float wrapped = floormod4(mm[i] + 2.0f) - 2.0f;

        const float d0 = (floormod4(wrapped - l0 + 2.0f) - 2.0f) * 0.5f;
        const float s0 = fsigmoid(S * d0);
        const float sc0 = 4.0f * s0 * (1.0f - s0);

        const float d1 = (floormod4(wrapped - l1 + 2.0f) - 2.0f) * 0.5f;
        const float s1 = fsigmoid(S * d1);
        const float sc1 = 4.0f * s1 * (1.0f - s1);

        // softmax over 2 entries with logits (sc+g)/2:
        // p1 = sigmoid(((sc1+g1)-(sc0+g0))/2); mask = l0 + (l1-l0)*p1
        const float p1   = fsigmoid(0.5f * ((sc1 + gg1[i]) - (sc0 + gg0[i])));
        const float mask = l0 + (l1 - l0) * p1;

        h[i] = mask * Ch + BASE_T;
    }

    const float lams[4] = {lam0, lam1, lam2, lam3};

    // ---- per-wavelength modulation ----
    #pragma unroll
    for (int w = 0; w < NW; w++) {
        const float k = 2.0f * PI * __fdividef(1.0f, lams[w]);
        const float A = -0.5f * k * td * sq;   // loss  = exp(A*h)
        const float B = k * (sq - 1.0f);       // phase = B*h, shift = loss*exp(-i*phase)

        const float4 fr = __ldcs((const float4*)field_r + w * HW4 + g);
        const float4 fi = __ldcs((const float4*)field_i + w * HW4 + g);
        const float frr[4] = {fr.x, fr.y, fr.z, fr.w};
        const float fii[4] = {fi.x, fi.y, fi.z, fi.w};

        float orr[4], oii[4];
        #pragma unroll
        for (int i = 0; i < 4; i++) {
            const float loss = __expf(A * h[i]);
            float s, c;
            __sincosf(B * h[i], &s, &c);
            const float psr =  loss * c;
            const float psi = -loss * s;
            // (fr + i*fi) * (psr + i*psi)
            orr[i] = frr[i] * psr - fii[i] * psi;
            oii[i] = frr[i] * psi + fii[i] * psr;
        }
        __stcs(&out4[w * HW4 + g],        make_float4(orr[0], orr[1], orr[2], orr[3]));
        __stcs(&out4[(NW + w) * HW4 + g], make_float4(oii[0], oii[1], oii[2], oii[3]));
    }
}

extern "C" void kernel_launch(void* const* d_in, const int* in_sizes, int n_in,
                              void* d_out, int out_size) {
    // metadata order: init_mask, lut, field_real, field_imag, wavelengths,
    //                 gumbel_noise, epsilon, tand
    const float* init_mask = (const float*)d_in[0];
    const float* lut       = (const float*)d_in[1];
    const float* field_r   = (const float*)d_in[2];
    const float* field_i   = (const float*)d_in[3];
    const float* wl        = (const float*)d_in[4];
    const float* gumbel    = (const float*)d_in[5];
    const float* eps       = (const float*)d_in[6];
    const float* td        = (const float*)d_in[7];

    const int threads = 256;
    const int blocks  = (HW4 + threads - 1) / threads;  // 4096
    sgqm_kernel<<<blocks, threads>>>(init_mask, lut, field_r, field_i,
                                     wl, gumbel, eps, td, (float*)d_out);
}

// round 4
// speedup vs baseline: 1.0625x; 1.0059x over previous
#include <cuda_runtime.h>
#include <cuda_bf16.h>

// Fixed shapes from setup_inputs
#define DIM   2048
#define HWTOT (DIM * DIM)
#define HW4   (HWTOT / 4)          // 1<<20 float4 groups per plane
#define NW    4
#define NPLANE (2 * NW)            // 8 output planes (re/im x 4 wavelengths)
// Aperture: |x_i| <= 0.04 with x_i = -0.1024 + i * (0.2048/2047)
// -> i in [624, 1423] (margin ~7e-5 m, fp32-safe). 624 % 4 == 0, 1424 % 4 == 0.
#define AP_LO 624
#define AP_HI 1423
#define AP_ROWS 800
#define AP_GPR  200                 // float4 groups per aperture row (800/4)
#define AP_G0   (AP_LO / 4)         // 156: first group column inside
#define GPR     (DIM / 4)           // 512 groups per full row

__device__ __forceinline__ float floormod4(float x) {
    return x - 4.0f * floorf(x * 0.25f);
}
__device__ __forceinline__ float fsigmoid(float x) {
    return __fdividef(1.0f, 1.0f + __expf(-x));
}

// ---------------------------------------------------------------------------
// Kernel A: zero-fill every output element OUTSIDE the aperture.
// Flat float4 index f over all 8 planes: plane = f >> 20, g = f & (HW4-1).
// Pure streaming stores; inside-aperture groups are skipped (kernel B owns them).
// ---------------------------------------------------------------------------
__global__ void __launch_bounds__(256)
sgqm_zero_kernel(float4* __restrict__ out4)
{
    const unsigned f = blockIdx.x * 256u + threadIdx.x;   // < NPLANE * HW4
    const unsigned g = f & (HW4 - 1u);
    const unsigned p = g << 2;
    const unsigned y = p >> 11;          // row
    const unsigned x = p & (DIM - 1u);   // first column of group

    const bool inside = (y >= AP_LO) & (y <= AP_HI) & (x >= AP_LO) & (x <= AP_HI);
    if (!inside) {
        __stcs(&out4[f], make_float4(0.f, 0.f, 0.f, 0.f));
    }
}

// ---------------------------------------------------------------------------
// Kernel B: compute the modulated field for the 800x800 aperture interior.
// One thread per float4 group; 160,000 groups = exactly 625 blocks x 256.
// All 11 float4 loads hoisted up front for maximum MLP.
// ---------------------------------------------------------------------------
__global__ void __launch_bounds__(256)
sgqm_aperture_kernel(const float* __restrict__ init_mask,
                     const float* __restrict__ lut,
                     const float* __restrict__ field_r,
                     const float* __restrict__ field_i,
                     const float* __restrict__ wl,
                     const float* __restrict__ gumbel,
                     const float* __restrict__ epsilon,
                     const float* __restrict__ tandp,
                     float* __restrict__ out)
{
    const int idx = blockIdx.x * 256 + threadIdx.x;       // < AP_ROWS*AP_GPR
    const int row_in  = idx / AP_GPR;                     // 0..799
    const int colg_in = idx - row_in * AP_GPR;            // 0..199
    const int g = (AP_LO + row_in) * GPR + AP_G0 + colg_in;

    // ---- hoisted bulk loads (11 independent LDG.128) ----
    const float4 m4  = __ldcs((const float4*)init_mask + g);
    const float4 gn0 = __ldcs((const float4*)gumbel + g);
    const float4 gn1 = __ldcs((const float4*)gumbel + HW4 + g);
    float4 fr[NW], fi[NW];
    #pragma unroll
    for (int w = 0; w < NW; w++) {
        fr[w] = __ldcs((const float4*)field_r + w * HW4 + g);
        fi[w] = __ldcs((const float4*)field_i + w * HW4 + g);
    }

    // ---- scalar parameters (L1-cached broadcasts) ----
    const float eps = __ldg(epsilon);
    const float td  = __ldg(tandp);
    const float sq  = sqrtf(eps);
    const float l0  = __ldg(lut);
    const float l1  = __ldg(lut + 1);
    const float lam0 = __ldg(wl + 0), lam1 = __ldg(wl + 1);
    const float lam2 = __ldg(wl + 2), lam3 = __ldg(wl + 3);
    const float lam_min = fminf(fminf(lam0, lam1), fminf(lam2, lam3));
    const float PI = 3.14159265358979323846f;
    const float Ch     = lam_min / (2.0f * (sq - 1.0f));  // height = mask*Ch
    const float BASE_T = 2.0e-3f;
    const float S      = 5.0f;

    // ---- per-pixel mask -> height ----
    const float mm[4]  = {m4.x,  m4.y,  m4.z,  m4.w};
    const float gg0[4] = {gn0.x, gn0.y, gn0.z, gn0.w};
    const float gg1[4] = {gn1.x, gn1.y, gn1.z, gn1.w};

    float h[4];
    #pragma unroll
    for (int i = 0; i < 4; i++) {
        const float wrapped = floormod4(mm[i] + 2.0f) - 2.0f;

        const float d0 = (floormod4(wrapped - l0 + 2.0f) - 2.0f) * 0.5f;
        const float s0 = fsigmoid(S * d0);
        const float sc0 = 4.0f * s0 * (1.0f - s0);

        const float d1 = (floormod4(wrapped - l1 + 2.0f) - 2.0f) * 0.5f;
        const float s1 = fsigmoid(S * d1);
        const float sc1 = 4.0f * s1 * (1.0f - s1);

        // 2-way gumbel softmax, logits (sc+g)/2
        const float p1   = fsigmoid(0.5f * ((sc1 + gg1[i]) - (sc0 + gg0[i])));
        const float mask = l0 + (l1 - l0) * p1;

        h[i] = mask * Ch + BASE_T;
    }

    const float lams[4] = {lam0, lam1, lam2, lam3};
    float4* __restrict__ out4 = (float4*)out;

    // ---- per-wavelength modulation ----
    #pragma unroll
    for (int w = 0; w < NW; w++) {
        const float k = 2.0f * PI * __fdividef(1.0f, lams[w]);
        const float A = -0.5f * k * td * sq;   // loss  = exp(A*h)
        const float B = k * (sq - 1.0f);       // phase = B*h

        const float frr[4] = {fr[w].x, fr[w].y, fr[w].z, fr[w].w};
        const float fii[4] = {fi[w].x, fi[w].y, fi[w].z, fi[w].w};

        float orr[4], oii[4];
        #pragma unroll
        for (int i = 0; i < 4; i++) {
            const float loss = __expf(A * h[i]);
            float s, c;
            __sincosf(B * h[i], &s, &c);
            const float psr =  loss * c;
            const float psi = -loss * s;
            orr[i] = frr[i] * psr - fii[i] * psi;
            oii[i] = frr[i] * psi + fii[i] * psr;
        }
        __stcs(&out4[w * HW4 + g],        make_float4(orr[0], orr[1], orr[2], orr[3]));
        __stcs(&out4[(NW + w) * HW4 + g], make_float4(oii[0], oii[1], oii[2], oii[3]));
    }
}

extern "C" void kernel_launch(void* const* d_in, const int* in_sizes, int n_in,
                              void* d_out, int out_size) {
    const float* init_mask = (const float*)d_in[0];
    const float* lut       = (const float*)d_in[1];
    const float* field_r   = (const float*)d_in[2];
    const float* field_i   = (const float*)d_in[3];
    const float* wl        = (const float*)d_in[4];
    const float* gumbel    = (const float*)d_in[5];
    const float* eps       = (const float*)d_in[6];
    const float* td        = (const float*)d_in[7];

    // Kernel A: zero-fill outside aperture (8M float4 slots, one thread each)
    {
        const int total = NPLANE * HW4;              // 8 * 2^20
        sgqm_zero_kernel<<<total / 256, 256>>>((float4*)d_out);
    }
    // Kernel B: aperture interior (exactly 625 blocks x 256 threads)
    {
        const int total = AP_ROWS * AP_GPR;          // 160000
        sgqm_aperture_kernel<<<total / 256, 256>>>(init_mask, lut, field_r, field_i,
                                                   wl, gumbel, eps, td, (float*)d_out);
    }
}